// round 9
// baseline (speedup 1.0000x reference)
#include <cuda_runtime.h>

// Problem constants
#define B_N    128
#define C_IN   256
#define OC_ALL 512
#define LXY    32
#define NPIX   1024       // 32*32
#define PW     35         // padded width/height (Lx + 3)

// Tiling
#define BDIM   128        // threads per block
#define CC     8          // input channels per smem stage
#define OCT    32         // output channels per block
#define TROWS  16         // output rows per block
// per-thread: 8 oc x 16 x-positions (8 float2 pairs)

__device__ __forceinline__ void ffma2(float2& d, const float2& a, const float2& b) {
    unsigned long long& dd = reinterpret_cast<unsigned long long&>(d);
    unsigned long long aa = *reinterpret_cast<const unsigned long long*>(&a);
    unsigned long long bb = *reinterpret_cast<const unsigned long long*>(&b);
    asm("fma.rn.f32x2 %0, %1, %2, %0;" : "+l"(dd) : "l"(aa), "l"(bb));
}

__global__ __launch_bounds__(BDIM, 2)
void conv_pbc_kernel(const float* __restrict__ x,
                     const float* __restrict__ W,
                     const float* __restrict__ bias,
                     float* __restrict__ out) {
    // pad tile: CC channels x 19 rows x 36 cols (35 valid + 1 slack, 144B row stride -> 16B aligned)
    __shared__ float pad_s[CC][19][36];
    // W tile transposed: [crs = c*16 + r*4 + s][oc], stride 36 for 16B-aligned float4 reads
    __shared__ float w_s[CC * 16][36];

    const int tid = threadIdx.x;
    const int ocg = tid & 3;          // 4 oc groups of 8
    const int xh  = (tid >> 2) & 1;   // x half: columns [xh*16, xh*16+16)
    const int row = tid >> 3;         // 0..15 local output row

    const int rowBase = blockIdx.x * TROWS;   // 0 or 16
    const int ocBase  = blockIdx.y * OCT;     // 0..480
    const int n       = blockIdx.z;           // image

    const float* xn = x + (size_t)n * C_IN * NPIX;

    float2 acc[8][8];
    #pragma unroll
    for (int o = 0; o < 8; o++)
        #pragma unroll
        for (int j = 0; j < 8; j++)
            acc[o][j] = make_float2(0.f, 0.f);

    for (int c0 = 0; c0 < C_IN; c0 += CC) {
        __syncthreads();

        // ---- load pad tile (on-the-fly PBC construction, coalesced over flat index) ----
        {
            const float* xp = xn + (size_t)c0 * NPIX;
            float* ps = &pad_s[0][0][0];
            for (int i = tid; i < CC * 19 * 36; i += BDIM) {
                int col = i % 36;
                int t   = i / 36;
                int lr  = t % 19;
                int cc  = t / 19;
                float v = 0.f;
                if (col < PW) {
                    int h = rowBase + lr;           // 0..34
                    int f = h * PW + col;           // flat index into (35x35)
                    const float* xc = xp + cc * NPIX;
                    if (f < NPIX) v = xc[f];
                    if (h >= LXY && col >= LXY) v += xc[(h - LXY) * LXY + (col - LXY)];
                }
                ps[i] = v;
            }
        }

        // ---- load W tile, transposed to [crs][oc] ----
        {
            const float* Wp = W + (size_t)ocBase * (C_IN * 16) + (size_t)c0 * 16;
            for (int i = tid; i < OCT * CC * 16; i += BDIM) {
                int o   = i >> 7;        // / (CC*16) = /128
                int crs = i & 127;       // c*16 + r*4 + s
                w_s[crs][o] = Wp[(size_t)o * (C_IN * 16) + crs];
            }
        }
        __syncthreads();

        // ---- compute ----
        #pragma unroll 1
        for (int cc = 0; cc < CC; cc++) {
            #pragma unroll 1
            for (int r = 0; r < 4; r++) {
                // 20-float row window covering all 4 s-offsets x 16 x-positions
                float v[20];
                const float4* vp = reinterpret_cast<const float4*>(&pad_s[cc][row + r][xh * 16]);
                #pragma unroll
                for (int q = 0; q < 5; q++) {
                    float4 t4 = vp[q];
                    v[q * 4 + 0] = t4.x; v[q * 4 + 1] = t4.y;
                    v[q * 4 + 2] = t4.z; v[q * 4 + 3] = t4.w;
                }
                #pragma unroll
                for (int s = 0; s < 4; s++) {
                    const float4* wp4 =
                        reinterpret_cast<const float4*>(&w_s[cc * 16 + r * 4 + s][ocg * 8]);
                    float4 wa = wp4[0];
                    float4 wb = wp4[1];
                    float2 w2[8];
                    w2[0] = make_float2(wa.x, wa.x); w2[1] = make_float2(wa.y, wa.y);
                    w2[2] = make_float2(wa.z, wa.z); w2[3] = make_float2(wa.w, wa.w);
                    w2[4] = make_float2(wb.x, wb.x); w2[5] = make_float2(wb.y, wb.y);
                    w2[6] = make_float2(wb.z, wb.z); w2[7] = make_float2(wb.w, wb.w);
                    #pragma unroll
                    for (int j = 0; j < 8; j++) {
                        float2 a = make_float2(v[2 * j + s], v[2 * j + s + 1]);
                        #pragma unroll
                        for (int o = 0; o < 8; o++)
                            ffma2(acc[o][j], a, w2[o]);
                    }
                }
            }
        }
    }

    // ---- epilogue: add bias, store 16 floats per oc as 4x float4 ----
    const int xbase = xh * 16;
    const int grow  = rowBase + row;
    #pragma unroll
    for (int o = 0; o < 8; o++) {
        int oc = ocBase + ocg * 8 + o;
        float bv = __ldg(&bias[oc]);
        float* op = out + (((size_t)n * OC_ALL + oc) * LXY + grow) * LXY + xbase;
        #pragma unroll
        for (int j = 0; j < 8; j += 2) {
            float4 st = make_float4(acc[o][j].x + bv,     acc[o][j].y + bv,
                                    acc[o][j + 1].x + bv, acc[o][j + 1].y + bv);
            reinterpret_cast<float4*>(op)[j >> 1] = st;
        }
    }
}

extern "C" void kernel_launch(void* const* d_in, const int* in_sizes, int n_in,
                              void* d_out, int out_size) {
    const float* x = (const float*)d_in[0];   // (128, 256, 32, 32) f32
    const float* W = (const float*)d_in[1];   // (512, 256, 4, 4)   f32
    const float* b = (const float*)d_in[2];   // (512,)             f32
    float* out = (float*)d_out;               // (128, 512, 32, 32) f32

    dim3 grid(LXY / TROWS, OC_ALL / OCT, B_N);   // (2, 16, 128)
    conv_pbc_kernel<<<grid, BDIM>>>(x, W, b, out);
}

// round 10
// speedup vs baseline: 1.7870x; 1.7870x over previous
#include <cuda_runtime.h>

// Problem constants
#define B_N    128
#define C_IN   256
#define OC_ALL 512
#define LXY    32
#define NPIX   1024       // 32*32
#define PW     35         // padded width/height (Lx + 3)

// Tiling
#define BDIM   128        // threads per block
#define CC     8          // input channels per smem stage
#define OCT    32         // output channels per block
#define TROWS  16         // output rows per block
// per-thread: 16 x-positions x 8 oc, as [16 x][4 oc-pair] float2 accumulators

#define PAD_ELEMS (19 * 36)   // 684 per channel

__device__ __forceinline__ void ffma2(float2& d, const float2& a, const float2& b) {
    unsigned long long& dd = reinterpret_cast<unsigned long long&>(d);
    unsigned long long aa = *reinterpret_cast<const unsigned long long*>(&a);
    unsigned long long bb = *reinterpret_cast<const unsigned long long*>(&b);
    asm("fma.rn.f32x2 %0, %1, %2, %0;" : "+l"(dd) : "l"(aa), "l"(bb));
}

__global__ __launch_bounds__(BDIM, 2)
void conv_pbc_kernel(const float* __restrict__ x,
                     const float* __restrict__ W,
                     const float* __restrict__ bias,
                     float* __restrict__ out) {
    // pad tile: CC channels x 19 rows x 36 cols (35 valid + slack; 144B rows, 16B aligned)
    __shared__ float pad_s[CC][19][36];
    // W tile transposed: [crs = c*16 + r*4 + s][oc]; stride 36 keeps float4 reads aligned
    __shared__ float w_s[CC * 16][36];

    const int tid = threadIdx.x;
    const int ocg = tid & 3;          // 4 oc groups of 8 (= 4 oc-pairs)
    const int xh  = (tid >> 2) & 1;   // x half: columns [xh*16, xh*16+16)
    const int row = tid >> 3;         // 0..15 local output row

    const int rowBase = blockIdx.x * TROWS;   // 0 or 16
    const int ocBase  = blockIdx.y * OCT;     // 0..480
    const int n       = blockIdx.z;           // image

    const float* xn = x + (size_t)n * C_IN * NPIX;

    // acc[j][p]: x position j (0..15), oc pair p; .x = oc 2p, .y = oc 2p+1
    float2 acc[16][4];
    #pragma unroll
    for (int j = 0; j < 16; j++)
        #pragma unroll
        for (int p = 0; p < 4; p++)
            acc[j][p] = make_float2(0.f, 0.f);

    for (int c0 = 0; c0 < C_IN; c0 += CC) {
        __syncthreads();

        // ---- pad tile loader: decompose (lr,col) once, reuse across all CC channels ----
        {
            const float* xp = xn + (size_t)c0 * NPIX;
            float* ps = &pad_s[0][0][0];
            #pragma unroll
            for (int it = 0; it < 6; it++) {
                int e = tid + it * BDIM;
                if (e < PAD_ELEMS) {
                    int lr  = e / 36;
                    int col = e - lr * 36;
                    int h   = rowBase + lr;           // 0..34
                    int f   = h * PW + col;           // flat index into 35x35
                    bool main_ok   = (col < PW) && (f < NPIX);
                    bool corner_ok = (col >= LXY) && (col < PW) && (h >= LXY);
                    int caddr = (h - LXY) * LXY + (col - LXY);
                    #pragma unroll
                    for (int cc = 0; cc < CC; cc++) {
                        const float* xc = xp + cc * NPIX;
                        float v = 0.f;
                        if (main_ok)   v  = xc[f];
                        if (corner_ok) v += xc[caddr];
                        ps[cc * PAD_ELEMS + e] = v;
                    }
                }
            }
        }

        // ---- W tile loader, transposed to [crs][oc] ----
        {
            const float* Wp = W + (size_t)ocBase * (C_IN * 16) + (size_t)c0 * 16;
            #pragma unroll
            for (int it = 0; it < (OCT * CC * 16) / BDIM; it++) {
                int i   = tid + it * BDIM;
                int o   = i >> 7;        // / 128
                int crs = i & 127;       // c*16 + r*4 + s
                w_s[crs][o] = Wp[(size_t)o * (C_IN * 16) + crs];
            }
        }
        __syncthreads();

        // ---- compute ----
        const float* ps = &pad_s[0][row][xh * 16];
        const float* ws = &w_s[0][ocg * 8];
        #pragma unroll 1
        for (int cc = 0; cc < CC; cc++) {
            #pragma unroll
            for (int r = 0; r < 4; r++) {
                // weights for 4 s-taps x 4 oc-pairs: float4 loads give aligned float2 pairs
                float2 w2[4][4];
                #pragma unroll
                for (int s = 0; s < 4; s++) {
                    const float4* wp4 = reinterpret_cast<const float4*>(
                        ws + (size_t)(cc * 16 + r * 4 + s) * 36);
                    float4 wa = wp4[0];
                    float4 wb = wp4[1];
                    w2[s][0] = make_float2(wa.x, wa.y);
                    w2[s][1] = make_float2(wa.z, wa.w);
                    w2[s][2] = make_float2(wb.x, wb.y);
                    w2[s][3] = make_float2(wb.z, wb.w);
                }
                // 19-pixel row window (loads 20)
                float v[20];
                const float4* vp = reinterpret_cast<const float4*>(
                    ps + (size_t)cc * PAD_ELEMS + r * 36);
                #pragma unroll
                for (int q = 0; q < 5; q++) {
                    float4 t4 = vp[q];
                    v[q * 4 + 0] = t4.x; v[q * 4 + 1] = t4.y;
                    v[q * 4 + 2] = t4.z; v[q * 4 + 3] = t4.w;
                }
                // per pixel k: one broadcast pack, fan out to all (s,p) consumers
                #pragma unroll
                for (int k = 0; k < 19; k++) {
                    float2 bv = make_float2(v[k], v[k]);
                    #pragma unroll
                    for (int s = 0; s < 4; s++) {
                        int j = k - s;
                        if (j >= 0 && j < 16) {
                            #pragma unroll
                            for (int p = 0; p < 4; p++)
                                ffma2(acc[j][p], bv, w2[s][p]);
                        }
                    }
                }
            }
        }
    }

    // ---- epilogue: add bias, store ----
    const int xbase = xh * 16;
    const int grow  = rowBase + row;
    #pragma unroll
    for (int p = 0; p < 4; p++) {
        int oc0 = ocBase + ocg * 8 + 2 * p;
        float b0 = __ldg(&bias[oc0]);
        float b1 = __ldg(&bias[oc0 + 1]);
        float* o0 = out + (((size_t)n * OC_ALL + oc0) * LXY + grow) * LXY + xbase;
        float* o1 = o0 + NPIX;   // next oc channel
        #pragma unroll
        for (int q = 0; q < 4; q++) {
            float4 s0 = make_float4(acc[4 * q + 0][p].x + b0, acc[4 * q + 1][p].x + b0,
                                    acc[4 * q + 2][p].x + b0, acc[4 * q + 3][p].x + b0);
            float4 s1 = make_float4(acc[4 * q + 0][p].y + b1, acc[4 * q + 1][p].y + b1,
                                    acc[4 * q + 2][p].y + b1, acc[4 * q + 3][p].y + b1);
            reinterpret_cast<float4*>(o0)[q] = s0;
            reinterpret_cast<float4*>(o1)[q] = s1;
        }
    }
}

extern "C" void kernel_launch(void* const* d_in, const int* in_sizes, int n_in,
                              void* d_out, int out_size) {
    const float* x = (const float*)d_in[0];   // (128, 256, 32, 32) f32
    const float* W = (const float*)d_in[1];   // (512, 256, 4, 4)   f32
    const float* b = (const float*)d_in[2];   // (512,)             f32
    float* out = (float*)d_out;               // (128, 512, 32, 32) f32

    dim3 grid(LXY / TROWS, OC_ALL / OCT, B_N);   // (2, 16, 128)
    conv_pbc_kernel<<<grid, BDIM>>>(x, W, b, out);
}

// round 11
// speedup vs baseline: 1.7910x; 1.0022x over previous
#include <cuda_runtime.h>

// Problem constants
#define B_N    128
#define C_IN   256
#define OC_ALL 512
#define LXY    32
#define NPIX   1024       // 32*32
#define PW     35         // padded width/height (Lx + 3)

// Tiling
#define BDIM   128        // threads per block
#define CC     8          // input channels per smem stage
#define OCT    32         // output channels per block
#define TROWS  16         // output rows per block
// per-thread: 16 x-positions x 8 oc, as [16 x][4 oc-pair] float2 accumulators

#define PAD_ELEMS (19 * 36)   // 684 per channel

__device__ __forceinline__ void ffma2(float2& d, const float2& a, const float2& b) {
    unsigned long long& dd = reinterpret_cast<unsigned long long&>(d);
    unsigned long long aa = *reinterpret_cast<const unsigned long long*>(&a);
    unsigned long long bb = *reinterpret_cast<const unsigned long long*>(&b);
    asm("fma.rn.f32x2 %0, %1, %2, %0;" : "+l"(dd) : "l"(aa), "l"(bb));
}

__global__ __launch_bounds__(BDIM, 2)
void conv_pbc_kernel(const float* __restrict__ x,
                     const float* __restrict__ W,
                     const float* __restrict__ bias,
                     float* __restrict__ out) {
    // pad tile: CC channels x 19 rows x 36 cols (35 valid + slack; 144B rows, 16B aligned)
    __shared__ float pad_s[CC][19][36];
    // W tile transposed: [crs = c*16 + r*4 + s][oc]; stride 36 keeps float4 reads aligned
    __shared__ float w_s[CC * 16][36];

    const int tid = threadIdx.x;
    const int ocg = tid & 3;          // 4 oc groups of 8 (= 4 oc-pairs)
    const int xh  = (tid >> 2) & 1;   // x half: columns [xh*16, xh*16+16)
    const int row = tid >> 3;         // 0..15 local output row

    const int rowBase = blockIdx.x * TROWS;   // 0 or 16
    const int ocBase  = blockIdx.y * OCT;     // 0..480
    const int n       = blockIdx.z;           // image

    const float* xn = x + (size_t)n * C_IN * NPIX;

    // acc[j][p]: x position j (0..15), oc pair p; .x = oc 2p, .y = oc 2p+1
    float2 acc[16][4];
    #pragma unroll
    for (int j = 0; j < 16; j++)
        #pragma unroll
        for (int p = 0; p < 4; p++)
            acc[j][p] = make_float2(0.f, 0.f);

    for (int c0 = 0; c0 < C_IN; c0 += CC) {
        __syncthreads();

        // ---- pad tile loader: decompose (lr,col) once, reuse across all CC channels ----
        {
            const float* xp = xn + (size_t)c0 * NPIX;
            float* ps = &pad_s[0][0][0];
            #pragma unroll
            for (int it = 0; it < 6; it++) {
                int e = tid + it * BDIM;
                if (e < PAD_ELEMS) {
                    int lr  = e / 36;
                    int col = e - lr * 36;
                    int h   = rowBase + lr;           // 0..34
                    int f   = h * PW + col;           // flat index into 35x35
                    bool main_ok   = (col < PW) && (f < NPIX);
                    bool corner_ok = (col >= LXY) && (col < PW) && (h >= LXY);
                    int caddr = (h - LXY) * LXY + (col - LXY);
                    #pragma unroll
                    for (int cc = 0; cc < CC; cc++) {
                        const float* xc = xp + cc * NPIX;
                        float v = 0.f;
                        if (main_ok)   v  = xc[f];
                        if (corner_ok) v += xc[caddr];
                        ps[cc * PAD_ELEMS + e] = v;
                    }
                }
            }
        }

        // ---- W tile loader, transposed to [crs][oc] ----
        {
            const float* Wp = W + (size_t)ocBase * (C_IN * 16) + (size_t)c0 * 16;
            #pragma unroll
            for (int it = 0; it < (OCT * CC * 16) / BDIM; it++) {
                int i   = tid + it * BDIM;
                int o   = i >> 7;        // / 128
                int crs = i & 127;       // c*16 + r*4 + s
                w_s[crs][o] = Wp[(size_t)o * (C_IN * 16) + crs];
            }
        }
        __syncthreads();

        // ---- compute ----
        const float* ps = &pad_s[0][row][xh * 16];
        const float* ws = &w_s[0][ocg * 8];
        #pragma unroll 1
        for (int cc = 0; cc < CC; cc++) {
            #pragma unroll
            for (int r = 0; r < 4; r++) {
                // weights for 4 s-taps x 4 oc-pairs: float4 loads give aligned float2 pairs
                float2 w2[4][4];
                #pragma unroll
                for (int s = 0; s < 4; s++) {
                    const float4* wp4 = reinterpret_cast<const float4*>(
                        ws + (size_t)(cc * 16 + r * 4 + s) * 36);
                    float4 wa = wp4[0];
                    float4 wb = wp4[1];
                    w2[s][0] = make_float2(wa.x, wa.y);
                    w2[s][1] = make_float2(wa.z, wa.w);
                    w2[s][2] = make_float2(wb.x, wb.y);
                    w2[s][3] = make_float2(wb.z, wb.w);
                }
                // 19-pixel row window (loads 20)
                float v[20];
                const float4* vp = reinterpret_cast<const float4*>(
                    ps + (size_t)cc * PAD_ELEMS + r * 36);
                #pragma unroll
                for (int q = 0; q < 5; q++) {
                    float4 t4 = vp[q];
                    v[q * 4 + 0] = t4.x; v[q * 4 + 1] = t4.y;
                    v[q * 4 + 2] = t4.z; v[q * 4 + 3] = t4.w;
                }
                // per pixel k: one broadcast pack, fan out to all (s,p) consumers
                #pragma unroll
                for (int k = 0; k < 19; k++) {
                    float2 bv = make_float2(v[k], v[k]);
                    #pragma unroll
                    for (int s = 0; s < 4; s++) {
                        int j = k - s;
                        if (j >= 0 && j < 16) {
                            #pragma unroll
                            for (int p = 0; p < 4; p++)
                                ffma2(acc[j][p], bv, w2[s][p]);
                        }
                    }
                }
            }
        }
    }

    // ---- epilogue: add bias, store ----
    const int xbase = xh * 16;
    const int grow  = rowBase + row;
    #pragma unroll
    for (int p = 0; p < 4; p++) {
        int oc0 = ocBase + ocg * 8 + 2 * p;
        float b0 = __ldg(&bias[oc0]);
        float b1 = __ldg(&bias[oc0 + 1]);
        float* o0 = out + (((size_t)n * OC_ALL + oc0) * LXY + grow) * LXY + xbase;
        float* o1 = o0 + NPIX;   // next oc channel
        #pragma unroll
        for (int q = 0; q < 4; q++) {
            float4 s0 = make_float4(acc[4 * q + 0][p].x + b0, acc[4 * q + 1][p].x + b0,
                                    acc[4 * q + 2][p].x + b0, acc[4 * q + 3][p].x + b0);
            float4 s1 = make_float4(acc[4 * q + 0][p].y + b1, acc[4 * q + 1][p].y + b1,
                                    acc[4 * q + 2][p].y + b1, acc[4 * q + 3][p].y + b1);
            reinterpret_cast<float4*>(o0)[q] = s0;
            reinterpret_cast<float4*>(o1)[q] = s1;
        }
    }
}

extern "C" void kernel_launch(void* const* d_in, const int* in_sizes, int n_in,
                              void* d_out, int out_size) {
    const float* x = (const float*)d_in[0];   // (128, 256, 32, 32) f32
    const float* W = (const float*)d_in[1];   // (512, 256, 4, 4)   f32
    const float* b = (const float*)d_in[2];   // (512,)             f32
    float* out = (float*)d_out;               // (128, 512, 32, 32) f32

    dim3 grid(LXY / TROWS, OC_ALL / OCT, B_N);   // (2, 16, 128)
    conv_pbc_kernel<<<grid, BDIM>>>(x, W, b, out);
}